// round 3
// baseline (speedup 1.0000x reference)
#include <cuda_runtime.h>
#include <cstdint>

#define BB 4
#define SS 512
#define DD 128
#define HH 8
#define SC_PITCH 516   // 516 % 32 == 4 -> 8 head lanes (stride 4 banks) conflict-free

// scratch (static device memory; no runtime allocation)
__device__ float g_q[BB*SS*DD];
__device__ float g_k[BB*SS*DD];
__device__ float g_v[BB*SS*DD];
__device__ float g_attn[BB*SS*DD];

// ---------------------------------------------------------------------------
// Kernel A: QKV projection. grid=256 (8 rows/block), block=384 (128 per matrix)
// ---------------------------------------------------------------------------
__global__ __launch_bounds__(384) void qkv_kernel(
    const float* __restrict__ x,
    const float* __restrict__ wq, const float* __restrict__ bq,
    const float* __restrict__ wk, const float* __restrict__ bk,
    const float* __restrict__ wv, const float* __restrict__ bv)
{
    __shared__ float xs[8][128];
    const int row0 = blockIdx.x * 8;
    const int t = threadIdx.x;

    if (t < 256) ((float4*)xs)[t] = ((const float4*)(x + (size_t)row0 * DD))[t];
    __syncthreads();

    const int mat = t >> 7;      // 0=q 1=k 2=v
    const int c   = t & 127;
    const float* W    = (mat == 0) ? wq : (mat == 1) ? wk : wv;
    const float* bias = (mat == 0) ? bq : (mat == 1) ? bk : bv;
    float* out        = (mat == 0) ? g_q : (mat == 1) ? g_k : g_v;

    float acc[8];
    #pragma unroll
    for (int r = 0; r < 8; r++) acc[r] = 0.f;

    #pragma unroll 8
    for (int d = 0; d < 128; d++) {
        float w = W[d * 128 + c];
        #pragma unroll
        for (int r = 0; r < 8; r++) acc[r] = fmaf(xs[r][d], w, acc[r]);
    }
    float bv_ = bias[c];
    #pragma unroll
    for (int r = 0; r < 8; r++) out[(size_t)(row0 + r) * DD + c] = acc[r] + bv_;
}

// ---------------------------------------------------------------------------
// Kernel B: fused st-bias + attention.
// grid = 256 (b = bx>>6, q0 = (bx&63)*8), block = 512, ~172KB dyn smem
// ---------------------------------------------------------------------------
__global__ __launch_bounds__(512, 1) void attn_kernel(
    const float* __restrict__ st, const int* __restrict__ mask,
    const float* __restrict__ wst)
{
    extern __shared__ float smem[];
    float* scores = smem;                               // [8][8][SC_PITCH]
    float* qs     = scores + 8 * 8 * SC_PITCH;          // [8][128]
    float* mask_s = qs + 8 * 128;                       // [512]
    float* rinv_s = mask_s + 512;                       // [64] (q*8+h)
    float* ks     = rinv_s + 64;                        // [64][129]; reused as outp[2][8][8][16]

    const int tid  = threadIdx.x;
    const int lane = tid & 31;
    const int wid  = tid >> 5;
    const int b    = blockIdx.x >> 6;
    const int q0   = (blockIdx.x & 63) * 8;

    // wst into registers: this lane owns d = 4*lane .. 4*lane+3
    float wreg[4][8];
    #pragma unroll
    for (int dd = 0; dd < 4; dd++)
        #pragma unroll
        for (int h = 0; h < 8; h++)
            wreg[dd][h] = wst[(4 * lane + dd) * HH + h];

    // stage q tile + mask
    if (tid < 256)
        ((float4*)qs)[tid] = ((const float4*)(g_q + (size_t)(b * SS + q0) * DD))[tid];
    mask_s[tid] = mask[b * SS + tid] ? -10000.0f : 0.0f;
    __syncthreads();

    // ---------------- Phase 1: qk^T / 4 into scores ----------------
    {
        const int q  = tid >> 6;   // 0..7
        const int kl = tid & 63;   // 0..63
        for (int kc = 0; kc < 8; kc++) {
            const float4* kg = (const float4*)(g_k + (size_t)(b * SS + kc * 64) * DD);
            #pragma unroll
            for (int idx = tid; idx < 64 * 32; idx += 512) {
                int r = idx >> 5, c4 = idx & 31;
                float4 kv = kg[r * 32 + c4];
                float* dst = ks + r * 129 + c4 * 4;
                dst[0] = kv.x; dst[1] = kv.y; dst[2] = kv.z; dst[3] = kv.w;
            }
            __syncthreads();

            float acc[8];
            #pragma unroll
            for (int h = 0; h < 8; h++) acc[h] = 0.f;
            const float* krow = ks + kl * 129;
            const float* qrow = qs + q * 128;
            #pragma unroll
            for (int e = 0; e < 128; e++)
                acc[e >> 4] = fmaf(qrow[e], krow[e], acc[e >> 4]);

            float* sdst = scores + (q * 8) * SC_PITCH + kc * 64 + kl;
            #pragma unroll
            for (int h = 0; h < 8; h++) sdst[h * SC_PITCH] = acc[h] * 0.25f;
            __syncthreads();
        }
    }

    // ---------------- Phase 2: st_emb bias (the 536MB stream) ----------------
    {
        // row (q*512+k) == task t; address = base + t*128 floats
        const float4* st4 = (const float4*)st + ((size_t)(b * SS + q0)) * SS * (DD / 4);
        float4 E[4];
        #pragma unroll
        for (int u = 0; u < 4; u++)
            E[u] = __ldcs(&st4[(size_t)(wid + u * 16) * 32 + lane]);

        for (int i = 0; i < 256; i += 4) {
            float4 En[4];
            {
                int ibase = (i + 4 < 256) ? (i + 4) : 0;   // safe dummy prefetch on last iter
                #pragma unroll
                for (int u = 0; u < 4; u++)
                    En[u] = __ldcs(&st4[(size_t)(wid + (ibase + u) * 16) * 32 + lane]);
            }
            #pragma unroll
            for (int u = 0; u < 4; u++) {
                const int t = wid + (i + u) * 16;
                const float4 e = E[u];
                float p[8];
                #pragma unroll
                for (int h = 0; h < 8; h++)
                    p[h] = fmaf(e.x, wreg[0][h],
                           fmaf(e.y, wreg[1][h],
                           fmaf(e.z, wreg[2][h], e.w * wreg[3][h])));
                // multi-value butterfly: 8 head sums in 9 shfls
                const bool hi = (lane & 16);
                #pragma unroll
                for (int j = 0; j < 4; j++) {
                    float give = hi ? p[j]     : p[j + 4];
                    float keep = hi ? p[j + 4] : p[j];
                    p[j] = keep + __shfl_xor_sync(0xffffffffu, give, 16);
                }
                const bool m8 = (lane & 8);
                #pragma unroll
                for (int j = 0; j < 2; j++) {
                    float give = m8 ? p[j]     : p[j + 2];
                    float keep = m8 ? p[j + 2] : p[j];
                    p[j] = keep + __shfl_xor_sync(0xffffffffu, give, 8);
                }
                {
                    const bool m4 = (lane & 4);
                    float give = m4 ? p[0] : p[1];
                    float keep = m4 ? p[1] : p[0];
                    p[0] = keep + __shfl_xor_sync(0xffffffffu, give, 4);
                }
                p[0] += __shfl_xor_sync(0xffffffffu, p[0], 2);
                p[0] += __shfl_xor_sync(0xffffffffu, p[0], 1);
                if ((lane & 3) == 0) {
                    const int h = lane >> 2;          // lane 4m holds head m
                    const int q = t >> 9, k = t & 511;
                    scores[(q * 8 + h) * SC_PITCH + k] += p[0];
                }
            }
            #pragma unroll
            for (int u = 0; u < 4; u++) E[u] = En[u];
        }
    }
    __syncthreads();

    // ---------------- Phase 3: softmax per (q,h) row ----------------
    for (int r = wid; r < 64; r += 16) {
        float* srow = scores + r * SC_PITCH;   // r == q*8+h, layout matches
        float vals[16];
        float mx = -1e30f;
        #pragma unroll
        for (int j = 0; j < 16; j++) {
            int k = lane + 32 * j;
            float v = srow[k] + mask_s[k];
            vals[j] = v;
            mx = fmaxf(mx, v);
        }
        #pragma unroll
        for (int o = 16; o > 0; o >>= 1) mx = fmaxf(mx, __shfl_xor_sync(0xffffffffu, mx, o));
        float sum = 0.f;
        #pragma unroll
        for (int j = 0; j < 16; j++) {
            float e = __expf(vals[j] - mx);
            srow[lane + 32 * j] = e;       // store unnormalized exp
            sum += e;
        }
        #pragma unroll
        for (int o = 16; o > 0; o >>= 1) sum += __shfl_xor_sync(0xffffffffu, sum, o);
        if (lane == 0) rinv_s[r] = 1.0f / sum;
    }
    __syncthreads();

    // ---------------- Phase 4: PV ----------------
    float* outp = ks;   // reuse: [2][8][8][16]
    {
        const int h  = wid & 7;
        const int kh = wid >> 3;       // k-half -> each v row read once per block
        const int e  = lane & 15;
        const int kk = lane >> 4;
        const float* vbase = g_v + (size_t)(b * SS) * DD + h * 16 + e;
        float acc[8];
        #pragma unroll
        for (int q = 0; q < 8; q++) acc[q] = 0.f;
        const int kend = kh * 256 + 256;
        for (int k = kh * 256 + kk; k < kend; k += 2) {
            float vv = vbase[(size_t)k * DD];
            #pragma unroll
            for (int q = 0; q < 8; q++)
                acc[q] = fmaf(scores[(q * 8 + h) * SC_PITCH + k], vv, acc[q]);
        }
        #pragma unroll
        for (int q = 0; q < 8; q++) acc[q] += __shfl_xor_sync(0xffffffffu, acc[q], 16);
        if (lane < 16) {
            #pragma unroll
            for (int q = 0; q < 8; q++)
                outp[((kh * 8 + h) * 8 + q) * 16 + e] = acc[q];
        }
    }
    __syncthreads();

    // combine halves, normalize, store
    #pragma unroll
    for (int id = tid; id < 1024; id += 512) {
        int e = id & 15, q = (id >> 4) & 7, h = id >> 7;
        float val = (outp[((0 * 8 + h) * 8 + q) * 16 + e] +
                     outp[((1 * 8 + h) * 8 + q) * 16 + e]) * rinv_s[q * 8 + h];
        g_attn[(size_t)(b * SS + q0 + q) * DD + h * 16 + e] = val;
    }
}

// ---------------------------------------------------------------------------
// Kernel C: out = LN(residual + attn @ wo + bo). grid=256 (8 rows), block=256
// ---------------------------------------------------------------------------
__global__ __launch_bounds__(256) void out_ln_kernel(
    const float* __restrict__ x, const float* __restrict__ wo,
    const float* __restrict__ bo, const float* __restrict__ g,
    const float* __restrict__ bbeta, float* __restrict__ out)
{
    __shared__ float as_[8][128];
    __shared__ float ys[8][128];
    const int row0 = blockIdx.x * 8;
    const int t = threadIdx.x;

    ((float4*)as_)[t] = ((const float4*)(g_attn + (size_t)row0 * DD))[t];
    __syncthreads();

    const int c  = t & 127;
    const int rg = t >> 7;   // rows rg*4 .. rg*4+3
    float acc[4] = {0.f, 0.f, 0.f, 0.f};
    #pragma unroll 8
    for (int d = 0; d < 128; d++) {
        float w = wo[d * 128 + c];
        #pragma unroll
        for (int r = 0; r < 4; r++) acc[r] = fmaf(as_[rg * 4 + r][d], w, acc[r]);
    }
    float bias = bo[c];
    #pragma unroll
    for (int r = 0; r < 4; r++)
        ys[rg * 4 + r][c] = acc[r] + bias + x[(size_t)(row0 + rg * 4 + r) * DD + c];
    __syncthreads();

    // LayerNorm: 8 warps, 1 row each
    const int wid = t >> 5, lane = t & 31;
    float4 v = ((float4*)ys[wid])[lane];
    float s = v.x + v.y + v.z + v.w;
    #pragma unroll
    for (int o = 16; o > 0; o >>= 1) s += __shfl_xor_sync(0xffffffffu, s, o);
    float mu = s * (1.f / 128.f);
    float dx = v.x - mu, dy = v.y - mu, dz = v.z - mu, dw = v.w - mu;
    float ss = dx * dx + dy * dy + dz * dz + dw * dw;
    #pragma unroll
    for (int o = 16; o > 0; o >>= 1) ss += __shfl_xor_sync(0xffffffffu, ss, o);
    float rstd = rsqrtf(ss * (1.f / 128.f) + 1e-5f);
    float4 gg = ((const float4*)g)[lane];
    float4 bb = ((const float4*)bbeta)[lane];
    float4 o4;
    o4.x = dx * rstd * gg.x + bb.x;
    o4.y = dy * rstd * gg.y + bb.y;
    o4.z = dz * rstd * gg.z + bb.z;
    o4.w = dw * rstd * gg.w + bb.w;
    ((float4*)(out + (size_t)(row0 + wid) * DD))[lane] = o4;
}

// ---------------------------------------------------------------------------
extern "C" void kernel_launch(void* const* d_in, const int* in_sizes, int n_in,
                              void* d_out, int out_size)
{
    const float* x    = (const float*)d_in[0];
    const float* st   = (const float*)d_in[1];
    const int*   mask = (const int*)  d_in[2];
    const float* wq   = (const float*)d_in[3];
    const float* bq   = (const float*)d_in[4];
    const float* wk   = (const float*)d_in[5];
    const float* bk   = (const float*)d_in[6];
    const float* wv   = (const float*)d_in[7];
    const float* bv   = (const float*)d_in[8];
    const float* wo   = (const float*)d_in[9];
    const float* bo   = (const float*)d_in[10];
    const float* wst  = (const float*)d_in[11];
    const float* lng  = (const float*)d_in[12];
    const float* lnb  = (const float*)d_in[13];
    float* out = (float*)d_out;

    const int SMEM_B = (8 * 8 * SC_PITCH + 8 * 128 + 512 + 64 + 64 * 129) * 4;
    cudaFuncSetAttribute(attn_kernel, cudaFuncAttributeMaxDynamicSharedMemorySize, SMEM_B);

    qkv_kernel<<<256, 384>>>(x, wq, bq, wk, bk, wv, bv);
    attn_kernel<<<256, 512, SMEM_B>>>(st, mask, wst);
    out_ln_kernel<<<256, 256>>>(x, wo, bo, lng, lnb, out);
}

// round 4
// speedup vs baseline: 1.0295x; 1.0295x over previous
#include <cuda_runtime.h>
#include <cstdint>

#define BB 4
#define SS 512
#define DD 128
#define HH 8
#define SC_PITCH 516

// scratch (static device memory; no runtime allocation)
__device__ float g_q[BB*SS*DD];
__device__ float g_k[BB*SS*DD];
__device__ float g_v[BB*SS*DD];
__device__ float g_attn[BB*SS*DD];
__device__ float g_bias[(size_t)BB*SS*SS*HH];   // [b*S+q][k][h], h innermost

// ---------------- f32x2 helpers ----------------
__device__ __forceinline__ unsigned long long pack2(float x) {
    unsigned long long r;
    asm("mov.b64 %0, {%1, %1};" : "=l"(r) : "f"(x));
    return r;
}
__device__ __forceinline__ void fma2(unsigned long long& d, unsigned long long a, unsigned long long b) {
    asm("fma.rn.f32x2 %0, %1, %2, %0;" : "+l"(d) : "l"(a), "l"(b));
}
__device__ __forceinline__ void unpack2(unsigned long long v, float& lo, float& hi) {
    asm("mov.b64 {%0, %1}, %2;" : "=f"(lo), "=f"(hi) : "l"(v));
}
__device__ __forceinline__ unsigned int smem_u32(const void* p) {
    return (unsigned int)__cvta_generic_to_shared(p);
}

// ---------------------------------------------------------------------------
// Kernel A: QKV projection. grid=128 (16 rows/block), block=384
// ---------------------------------------------------------------------------
__global__ __launch_bounds__(384) void qkv_kernel(
    const float* __restrict__ x,
    const float* __restrict__ wq, const float* __restrict__ bq,
    const float* __restrict__ wk, const float* __restrict__ bk,
    const float* __restrict__ wv, const float* __restrict__ bv)
{
    __shared__ float xs[16][128];
    const int row0 = blockIdx.x * 16;
    const int t = threadIdx.x;

    for (int i = t; i < 512; i += 384)
        ((float4*)xs)[i] = ((const float4*)(x + (size_t)row0 * DD))[i];
    __syncthreads();

    const int mat = t >> 7;      // 0=q 1=k 2=v
    const int tl  = t & 127;
    const int c4  = tl & 31;
    const int rg  = tl >> 5;     // rows rg*4 .. rg*4+3
    const float* W    = (mat == 0) ? wq : (mat == 1) ? wk : wv;
    const float* bias = (mat == 0) ? bq : (mat == 1) ? bk : bv;
    float* out        = (mat == 0) ? g_q : (mat == 1) ? g_k : g_v;
    const ulonglong2* W2 = (const ulonglong2*)W;

    unsigned long long acc[4][2];
    #pragma unroll
    for (int r = 0; r < 4; r++) { acc[r][0] = 0ull; acc[r][1] = 0ull; }

    #pragma unroll 8
    for (int d = 0; d < 128; d++) {
        ulonglong2 w = W2[d * 32 + c4];
        #pragma unroll
        for (int r = 0; r < 4; r++) {
            unsigned long long xr = pack2(xs[rg * 4 + r][d]);
            fma2(acc[r][0], xr, w.x);
            fma2(acc[r][1], xr, w.y);
        }
    }
    float4 bb = ((const float4*)bias)[c4];
    #pragma unroll
    for (int r = 0; r < 4; r++) {
        float4 o;
        unpack2(acc[r][0], o.x, o.y);
        unpack2(acc[r][1], o.z, o.w);
        o.x += bb.x; o.y += bb.y; o.z += bb.z; o.w += bb.w;
        ((float4*)(out + (size_t)(row0 + rg * 4 + r) * DD))[c4] = o;
    }
}

// ---------------------------------------------------------------------------
// Kernel B: st_bias stream. bias[bq][k][h] = sum_d st[bq][k][d] * wst[d][h]
// block=256 (8 warps), grid=444, 70KB smem, 3 blocks/SM (24 warps).
// Each warp handles units of 16 k-rows; lane = (row r=lane>>1, h-half hh=lane&1).
// ---------------------------------------------------------------------------
#define BIAS_GRID 444
__global__ __launch_bounds__(256, 3) void bias_kernel(
    const float* __restrict__ st, const float* __restrict__ wst)
{
    extern __shared__ float sm[];
    float4* w2 = (float4*)sm;                 // [128][2] : (d, h-half) -> 4 heads
    float* stage_base = sm + 1024;            // 8 warps x [16][132]

    const int tid  = threadIdx.x;
    const int lane = tid & 31;
    const int wid  = tid >> 5;

    // init packed wst: entry (d, hh) = wst[d*8 + hh*4 .. +3]
    for (int i = tid; i < 256; i += 256) {
        int d = i >> 1, hh = i & 1;
        const float* ws = wst + d * HH + hh * 4;
        w2[i] = make_float4(ws[0], ws[1], ws[2], ws[3]);
    }
    __syncthreads();

    float* stg = stage_base + wid * (16 * 132);
    const unsigned int stg_u32 = smem_u32(stg);
    const int r  = lane >> 1;
    const int hh = lane & 1;
    const float4* myrow = (const float4*)stg + r * 33;
    const ulonglong2* wsel = (const ulonglong2*)w2 + hh;   // + d*2

    const int gw = blockIdx.x * 8 + wid;
    const int nw = BIAS_GRID * 8;

    for (int u = gw; u < 65536; u += nw) {
        const int bq = u >> 5;
        const int k0 = (u & 31) * 16;

        __syncwarp();
        // stage 16 rows (16 x 128 floats) via cp.async, swizzle-free pitch 132
        {
            const char* gsrc = (const char*)(st + ((size_t)bq * SS + k0) * DD) + lane * 16;
            unsigned int sdst = stg_u32 + lane * 16;
            #pragma unroll
            for (int it = 0; it < 16; it++) {
                asm volatile("cp.async.cg.shared.global [%0], [%1], 16;"
                             :: "r"(sdst + it * 33 * 16), "l"(gsrc + (size_t)it * 512)
                             : "memory");
            }
            asm volatile("cp.async.commit_group;");
            asm volatile("cp.async.wait_group 0;" ::: "memory");
        }
        __syncwarp();

        unsigned long long a0 = 0ull, a1 = 0ull;   // 4 heads (hh*4 .. hh*4+3)
        #pragma unroll 8
        for (int j = 0; j < 32; j++) {
            float4 e = myrow[j];
            {
                ulonglong2 w = wsel[(4 * j + 0) * 2];
                unsigned long long ee = pack2(e.x);
                fma2(a0, ee, w.x); fma2(a1, ee, w.y);
            }
            {
                ulonglong2 w = wsel[(4 * j + 1) * 2];
                unsigned long long ee = pack2(e.y);
                fma2(a0, ee, w.x); fma2(a1, ee, w.y);
            }
            {
                ulonglong2 w = wsel[(4 * j + 2) * 2];
                unsigned long long ee = pack2(e.z);
                fma2(a0, ee, w.x); fma2(a1, ee, w.y);
            }
            {
                ulonglong2 w = wsel[(4 * j + 3) * 2];
                unsigned long long ee = pack2(e.w);
                fma2(a0, ee, w.x); fma2(a1, ee, w.y);
            }
        }
        float4 o;
        unpack2(a0, o.x, o.y);
        unpack2(a1, o.z, o.w);
        float4* dst = (float4*)(g_bias + ((size_t)bq * SS + k0 + r) * HH) + hh;
        __stcs(dst, o);
    }
}

// ---------------------------------------------------------------------------
// Kernel C: attention (qk + bias + mask + softmax + PV).
// grid = 256 (b = bx>>6, q0 = (bx&63)*8), block = 512, ~168KB dyn smem
// ---------------------------------------------------------------------------
__global__ __launch_bounds__(512, 1) void attn_kernel(const int* __restrict__ mask)
{
    extern __shared__ float smem[];
    float* scores = smem;                               // [8][8][SC_PITCH]
    float* qs     = scores + 8 * 8 * SC_PITCH;          // [8][128]
    float* mask_s = qs + 8 * 128;                       // [512]
    float* rinv_s = mask_s + 512;                       // [64] (q*8+h)
    float* ks     = rinv_s + 64;                        // [64][132]; reused as outp[2][8][8][16]

    const int tid  = threadIdx.x;
    const int lane = tid & 31;
    const int wid  = tid >> 5;
    const int b    = blockIdx.x >> 6;
    const int q0   = (blockIdx.x & 63) * 8;

    if (tid < 256)
        ((float4*)qs)[tid] = ((const float4*)(g_q + (size_t)(b * SS + q0) * DD))[tid];
    mask_s[tid] = mask[b * SS + tid] ? -10000.0f : 0.0f;
    __syncthreads();

    // ---------------- Phase 1: scores = qk/4 + bias ----------------
    {
        const int q  = tid >> 6;   // 0..7
        const int kl = tid & 63;   // 0..63
        for (int kc = 0; kc < 8; kc++) {
            const float4* kg = (const float4*)(g_k + (size_t)(b * SS + kc * 64) * DD);
            #pragma unroll
            for (int idx = tid; idx < 64 * 32; idx += 512)
                ((float4*)ks)[(idx >> 5) * 33 + (idx & 31)] = kg[idx];
            __syncthreads();

            float acc[8];
            #pragma unroll
            for (int h = 0; h < 8; h++) acc[h] = 0.f;
            const float4* kr = (const float4*)ks + kl * 33;
            const float4* qr = (const float4*)qs + q * 32;
            #pragma unroll
            for (int j = 0; j < 32; j++) {
                float4 a = qr[j], c = kr[j];
                acc[j >> 2] = fmaf(a.x, c.x, fmaf(a.y, c.y,
                              fmaf(a.z, c.z, fmaf(a.w, c.w, acc[j >> 2]))));
            }
            const float4* brow = (const float4*)(g_bias +
                ((size_t)(b * SS + q0 + q) * SS + kc * 64 + kl) * HH);
            float4 b0 = __ldg(brow);
            float4 b1 = __ldg(brow + 1);
            float bh[8] = {b0.x, b0.y, b0.z, b0.w, b1.x, b1.y, b1.z, b1.w};

            float* sdst = scores + (q * 8) * SC_PITCH + kc * 64 + kl;
            #pragma unroll
            for (int h = 0; h < 8; h++) sdst[h * SC_PITCH] = fmaf(acc[h], 0.25f, bh[h]);
            __syncthreads();
        }
    }

    // ---------------- Phase 2: softmax per (q,h) row ----------------
    for (int rr = wid; rr < 64; rr += 16) {
        float* srow = scores + rr * SC_PITCH;
        float vals[16];
        float mx = -1e30f;
        #pragma unroll
        for (int j = 0; j < 16; j++) {
            int k = lane + 32 * j;
            float v = srow[k] + mask_s[k];
            vals[j] = v;
            mx = fmaxf(mx, v);
        }
        #pragma unroll
        for (int o = 16; o > 0; o >>= 1) mx = fmaxf(mx, __shfl_xor_sync(0xffffffffu, mx, o));
        float sum = 0.f;
        #pragma unroll
        for (int j = 0; j < 16; j++) {
            float e = __expf(vals[j] - mx);
            srow[lane + 32 * j] = e;
            sum += e;
        }
        #pragma unroll
        for (int o = 16; o > 0; o >>= 1) sum += __shfl_xor_sync(0xffffffffu, sum, o);
        if (lane == 0) rinv_s[rr] = 1.0f / sum;
    }
    __syncthreads();

    // ---------------- Phase 3: PV ----------------
    float* outp = ks;   // reuse: [2][8][8][16]
    {
        const int h  = wid & 7;
        const int kh = wid >> 3;
        const int e  = lane & 15;
        const int kk = lane >> 4;
        const float* vbase = g_v + (size_t)(b * SS) * DD + h * 16 + e;
        float acc[8];
        #pragma unroll
        for (int q = 0; q < 8; q++) acc[q] = 0.f;
        const int kend = kh * 256 + 256;
        for (int k = kh * 256 + kk; k < kend; k += 2) {
            float vv = vbase[(size_t)k * DD];
            #pragma unroll
            for (int q = 0; q < 8; q++)
                acc[q] = fmaf(scores[(q * 8 + h) * SC_PITCH + k], vv, acc[q]);
        }
        #pragma unroll
        for (int q = 0; q < 8; q++) acc[q] += __shfl_xor_sync(0xffffffffu, acc[q], 16);
        if (lane < 16) {
            #pragma unroll
            for (int q = 0; q < 8; q++)
                outp[((kh * 8 + h) * 8 + q) * 16 + e] = acc[q];
        }
    }
    __syncthreads();

    #pragma unroll
    for (int id = tid; id < 1024; id += 512) {
        int e = id & 15, q = (id >> 4) & 7, h = id >> 7;
        float val = (outp[((0 * 8 + h) * 8 + q) * 16 + e] +
                     outp[((1 * 8 + h) * 8 + q) * 16 + e]) * rinv_s[q * 8 + h];
        g_attn[(size_t)(b * SS + q0 + q) * DD + h * 16 + e] = val;
    }
}

// ---------------------------------------------------------------------------
// Kernel D: out = LN(residual + attn @ wo + bo). grid=256 (8 rows), block=256
// ---------------------------------------------------------------------------
__global__ __launch_bounds__(256) void out_ln_kernel(
    const float* __restrict__ x, const float* __restrict__ wo,
    const float* __restrict__ bo, const float* __restrict__ g,
    const float* __restrict__ bbeta, float* __restrict__ out)
{
    __shared__ float as_[8][128];
    __shared__ float ys[8][128];
    const int row0 = blockIdx.x * 8;
    const int t = threadIdx.x;

    ((float4*)as_)[t] = ((const float4*)(g_attn + (size_t)row0 * DD))[t];
    __syncthreads();

    const int c  = t & 127;
    const int rg = t >> 7;
    float acc[4] = {0.f, 0.f, 0.f, 0.f};
    #pragma unroll 8
    for (int d = 0; d < 128; d++) {
        float w = wo[d * 128 + c];
        #pragma unroll
        for (int r = 0; r < 4; r++) acc[r] = fmaf(as_[rg * 4 + r][d], w, acc[r]);
    }
    float bias = bo[c];
    #pragma unroll
    for (int r = 0; r < 4; r++)
        ys[rg * 4 + r][c] = acc[r] + bias + x[(size_t)(row0 + rg * 4 + r) * DD + c];
    __syncthreads();

    const int wid = t >> 5, lane = t & 31;
    float4 v = ((float4*)ys[wid])[lane];
    float s = v.x + v.y + v.z + v.w;
    #pragma unroll
    for (int o = 16; o > 0; o >>= 1) s += __shfl_xor_sync(0xffffffffu, s, o);
    float mu = s * (1.f / 128.f);
    float dx = v.x - mu, dy = v.y - mu, dz = v.z - mu, dw = v.w - mu;
    float ss = dx * dx + dy * dy + dz * dz + dw * dw;
    #pragma unroll
    for (int o = 16; o > 0; o >>= 1) ss += __shfl_xor_sync(0xffffffffu, ss, o);
    float rstd = rsqrtf(ss * (1.f / 128.f) + 1e-5f);
    float4 gg = ((const float4*)g)[lane];
    float4 bb = ((const float4*)bbeta)[lane];
    float4 o4;
    o4.x = dx * rstd * gg.x + bb.x;
    o4.y = dy * rstd * gg.y + bb.y;
    o4.z = dz * rstd * gg.z + bb.z;
    o4.w = dw * rstd * gg.w + bb.w;
    ((float4*)(out + (size_t)(row0 + wid) * DD))[lane] = o4;
}

// ---------------------------------------------------------------------------
extern "C" void kernel_launch(void* const* d_in, const int* in_sizes, int n_in,
                              void* d_out, int out_size)
{
    const float* x    = (const float*)d_in[0];
    const float* st   = (const float*)d_in[1];
    const int*   mask = (const int*)  d_in[2];
    const float* wq   = (const float*)d_in[3];
    const float* bq   = (const float*)d_in[4];
    const float* wk   = (const float*)d_in[5];
    const float* bk   = (const float*)d_in[6];
    const float* wv   = (const float*)d_in[7];
    const float* bv   = (const float*)d_in[8];
    const float* wo   = (const float*)d_in[9];
    const float* bo   = (const float*)d_in[10];
    const float* wst  = (const float*)d_in[11];
    const float* lng  = (const float*)d_in[12];
    const float* lnb  = (const float*)d_in[13];
    float* out = (float*)d_out;

    const int SMEM_BIAS = (1024 + 8 * 16 * 132) * 4;                        // 71680 B
    const int SMEM_ATTN = (8 * 8 * SC_PITCH + 8 * 128 + 512 + 64 + 64 * 132) * 4; // 172288 B
    cudaFuncSetAttribute(bias_kernel, cudaFuncAttributeMaxDynamicSharedMemorySize, SMEM_BIAS);
    cudaFuncSetAttribute(attn_kernel, cudaFuncAttributeMaxDynamicSharedMemorySize, SMEM_ATTN);

    bias_kernel<<<BIAS_GRID, 256, SMEM_BIAS>>>(st, wst);
    qkv_kernel<<<128, 384>>>(x, wq, bq, wk, bk, wv, bv);
    attn_kernel<<<256, 512, SMEM_ATTN>>>(mask);
    out_ln_kernel<<<256, 256>>>(x, wo, bo, lng, lnb, out);
}

// round 5
// speedup vs baseline: 1.0806x; 1.0496x over previous
#include <cuda_runtime.h>
#include <cstdint>

#define BB 4
#define SS 512
#define DD 128
#define HH 8
#define SC_PITCH 516

// scratch (static device memory; no runtime allocation)
__device__ float g_q[BB*SS*DD];
__device__ float g_k[BB*SS*DD];
__device__ float g_v[BB*SS*DD];
__device__ float g_attn[BB*SS*DD];
__device__ float g_bias[(size_t)BB*SS*SS*HH];   // [b*S+q][k][h], h innermost

// ---------------- f32x2 helpers ----------------
__device__ __forceinline__ unsigned long long pack2(float x) {
    unsigned long long r;
    asm("mov.b64 %0, {%1, %1};" : "=l"(r) : "f"(x));
    return r;
}
__device__ __forceinline__ unsigned long long pack2v(float lo, float hi) {
    unsigned long long r;
    asm("mov.b64 %0, {%1, %2};" : "=l"(r) : "f"(lo), "f"(hi));
    return r;
}
__device__ __forceinline__ void fma2(unsigned long long& d, unsigned long long a, unsigned long long b) {
    asm("fma.rn.f32x2 %0, %1, %2, %0;" : "+l"(d) : "l"(a), "l"(b));
}
__device__ __forceinline__ void unpack2(unsigned long long v, float& lo, float& hi) {
    asm("mov.b64 {%0, %1}, %2;" : "=f"(lo), "=f"(hi) : "l"(v));
}
__device__ __forceinline__ unsigned int smem_u32(const void* p) {
    return (unsigned int)__cvta_generic_to_shared(p);
}

// ---------------------------------------------------------------------------
// Kernel A: QKV projection. grid=128 (16 rows/block), block=384
// ---------------------------------------------------------------------------
__global__ __launch_bounds__(384) void qkv_kernel(
    const float* __restrict__ x,
    const float* __restrict__ wq, const float* __restrict__ bq,
    const float* __restrict__ wk, const float* __restrict__ bk,
    const float* __restrict__ wv, const float* __restrict__ bv)
{
    __shared__ float xs[16][128];
    const int row0 = blockIdx.x * 16;
    const int t = threadIdx.x;

    for (int i = t; i < 512; i += 384)
        ((float4*)xs)[i] = ((const float4*)(x + (size_t)row0 * DD))[i];
    __syncthreads();

    const int mat = t >> 7;      // 0=q 1=k 2=v
    const int tl  = t & 127;
    const int c4  = tl & 31;
    const int rg  = tl >> 5;     // rows rg*4 .. rg*4+3
    const float* W    = (mat == 0) ? wq : (mat == 1) ? wk : wv;
    const float* bias = (mat == 0) ? bq : (mat == 1) ? bk : bv;
    float* out        = (mat == 0) ? g_q : (mat == 1) ? g_k : g_v;
    const ulonglong2* W2 = (const ulonglong2*)W;

    unsigned long long acc[4][2];
    #pragma unroll
    for (int r = 0; r < 4; r++) { acc[r][0] = 0ull; acc[r][1] = 0ull; }

    #pragma unroll 8
    for (int d = 0; d < 128; d++) {
        ulonglong2 w = W2[d * 32 + c4];
        #pragma unroll
        for (int r = 0; r < 4; r++) {
            unsigned long long xr = pack2(xs[rg * 4 + r][d]);
            fma2(acc[r][0], xr, w.x);
            fma2(acc[r][1], xr, w.y);
        }
    }
    float4 bb = ((const float4*)bias)[c4];
    #pragma unroll
    for (int r = 0; r < 4; r++) {
        float4 o;
        unpack2(acc[r][0], o.x, o.y);
        unpack2(acc[r][1], o.z, o.w);
        o.x += bb.x; o.y += bb.y; o.z += bb.z; o.w += bb.w;
        ((float4*)(out + (size_t)(row0 + rg * 4 + r) * DD))[c4] = o;
    }
}

// ---------------------------------------------------------------------------
// Kernel B: st_bias stream, double-buffered cp.async pipeline.
// grid=148, block=256 (8 warps), 1 CTA/SM, ~139KB smem.
// Task = 16 k-rows. lane = (row r=lane>>1, h-half hh=lane&1).
// ---------------------------------------------------------------------------
#define BIAS_GRID 148
#define STG_F (16 * 132)   // floats per staging buffer
__global__ __launch_bounds__(256, 1) void bias_kernel(
    const float* __restrict__ st, const float* __restrict__ wst)
{
    extern __shared__ float sm[];
    float4* w2 = (float4*)sm;                 // [128][2] : (d, h-half) -> 4 heads
    float* stage_base = sm + 1024;            // 8 warps x 2 bufs x [16][132]

    const int tid  = threadIdx.x;
    const int lane = tid & 31;
    const int wid  = tid >> 5;

    // init packed wst: entry (d, hh) = wst[d*8 + hh*4 .. +3]
    {
        int d = tid >> 1, hh = tid & 1;
        const float* ws = wst + d * HH + hh * 4;
        w2[tid] = make_float4(ws[0], ws[1], ws[2], ws[3]);
    }
    __syncthreads();

    float* stg0 = stage_base + wid * (2 * STG_F);
    const unsigned int stg_u32_0 = smem_u32(stg0);
    const int r  = lane >> 1;
    const int hh = lane & 1;
    const ulonglong2* wsel = (const ulonglong2*)w2 + hh;   // + d*2

    const int gw = blockIdx.x * 8 + wid;
    const int nw = BIAS_GRID * 8;

    // prefetch helper (macro to keep addresses simple)
    #define BIAS_PREFETCH(task, bufidx) do {                                          \
        const int bq_ = (task) >> 5;                                                  \
        const int k0_ = ((task) & 31) * 16;                                           \
        const char* gsrc = (const char*)(st + ((size_t)bq_ * SS + k0_) * DD) + lane * 16; \
        unsigned int sdst = stg_u32_0 + (bufidx) * (STG_F * 4) + lane * 16;           \
        _Pragma("unroll")                                                             \
        for (int it = 0; it < 16; it++) {                                             \
            asm volatile("cp.async.cg.shared.global [%0], [%1], 16;"                  \
                         :: "r"(sdst + it * 132 * 4), "l"(gsrc + (size_t)it * 512)    \
                         : "memory");                                                 \
        }                                                                             \
        asm volatile("cp.async.commit_group;");                                       \
    } while (0)

    int buf = 0;
    if (gw < 65536) { BIAS_PREFETCH(gw, 0); }

    for (int u = gw; u < 65536; u += nw) {
        const int un  = u + nw;
        const int upf = (un < 65536) ? un : gw;   // dummy tail prefetch keeps wait_group 1 correct
        BIAS_PREFETCH(upf, buf ^ 1);

        asm volatile("cp.async.wait_group 1;" ::: "memory");
        __syncwarp();

        const float4* myrow = (const float4*)(stg0 + buf * STG_F) + r * 33;

        unsigned long long a0 = 0ull, a1 = 0ull;   // 4 heads (hh*4 .. hh*4+3)
        #pragma unroll 8
        for (int j = 0; j < 32; j++) {
            float4 e = myrow[j];
            {
                ulonglong2 w = wsel[(4 * j + 0) * 2];
                unsigned long long ee = pack2(e.x);
                fma2(a0, ee, w.x); fma2(a1, ee, w.y);
            }
            {
                ulonglong2 w = wsel[(4 * j + 1) * 2];
                unsigned long long ee = pack2(e.y);
                fma2(a0, ee, w.x); fma2(a1, ee, w.y);
            }
            {
                ulonglong2 w = wsel[(4 * j + 2) * 2];
                unsigned long long ee = pack2(e.z);
                fma2(a0, ee, w.x); fma2(a1, ee, w.y);
            }
            {
                ulonglong2 w = wsel[(4 * j + 3) * 2];
                unsigned long long ee = pack2(e.w);
                fma2(a0, ee, w.x); fma2(a1, ee, w.y);
            }
        }
        float4 o;
        unpack2(a0, o.x, o.y);
        unpack2(a1, o.z, o.w);
        const int bq = u >> 5;
        const int k0 = (u & 31) * 16;
        float4* dst = (float4*)(g_bias + ((size_t)bq * SS + k0 + r) * HH) + hh;
        *dst = o;                       // plain store: keep in L2 for attn

        __syncwarp();                   // protect buf before it is re-prefetched
        buf ^= 1;
    }
    #undef BIAS_PREFETCH
}

// ---------------------------------------------------------------------------
// Kernel C: attention (qk + bias + mask + softmax + PV).
// grid = 256 (b = bx>>6, q0 = (bx&63)*8), block = 512, ~168KB dyn smem
// ---------------------------------------------------------------------------
__global__ __launch_bounds__(512, 1) void attn_kernel(const int* __restrict__ mask)
{
    extern __shared__ float smem[];
    float* scores = smem;                               // [8][8][SC_PITCH]
    float* qs     = scores + 8 * 8 * SC_PITCH;          // [8][128]
    float* mask_s = qs + 8 * 128;                       // [512]
    float* rinv_s = mask_s + 512;                       // [64] (q*8+h)
    float* ks     = rinv_s + 64;                        // [64][132]; reused as outp[2][8][8][16]

    const int tid  = threadIdx.x;
    const int lane = tid & 31;
    const int wid  = tid >> 5;
    const int b    = blockIdx.x >> 6;
    const int q0   = (blockIdx.x & 63) * 8;

    if (tid < 256)
        ((float4*)qs)[tid] = ((const float4*)(g_q + (size_t)(b * SS + q0) * DD))[tid];
    mask_s[tid] = mask[b * SS + tid] ? -10000.0f : 0.0f;
    __syncthreads();

    // ---------------- Phase 1: scores = qk/4 + bias ----------------
    {
        const int q  = tid >> 6;   // 0..7
        const int kl = tid & 63;   // 0..63
        for (int kc = 0; kc < 8; kc++) {
            const float4* kg = (const float4*)(g_k + (size_t)(b * SS + kc * 64) * DD);
            #pragma unroll
            for (int idx = tid; idx < 64 * 32; idx += 512)
                ((float4*)ks)[(idx >> 5) * 33 + (idx & 31)] = kg[idx];
            __syncthreads();

            unsigned long long acc2[8];
            #pragma unroll
            for (int h = 0; h < 8; h++) acc2[h] = 0ull;
            const ulonglong2* kr = (const ulonglong2*)(ks + kl * 132);
            const ulonglong2* qr = (const ulonglong2*)(qs + q * 128);
            #pragma unroll
            for (int j = 0; j < 32; j++) {
                ulonglong2 a = qr[j], c = kr[j];
                fma2(acc2[j >> 2], a.x, c.x);
                fma2(acc2[j >> 2], a.y, c.y);
            }
            const float4* brow = (const float4*)(g_bias +
                ((size_t)(b * SS + q0 + q) * SS + kc * 64 + kl) * HH);
            float4 b0 = __ldg(brow);
            float4 b1 = __ldg(brow + 1);
            float bh[8] = {b0.x, b0.y, b0.z, b0.w, b1.x, b1.y, b1.z, b1.w};

            float* sdst = scores + (q * 8) * SC_PITCH + kc * 64 + kl;
            #pragma unroll
            for (int h = 0; h < 8; h++) {
                float lo, hi;
                unpack2(acc2[h], lo, hi);
                sdst[h * SC_PITCH] = fmaf(lo + hi, 0.25f, bh[h]);
            }
            __syncthreads();
        }
    }

    // ---------------- Phase 2: softmax per (q,h) row ----------------
    for (int rr = wid; rr < 64; rr += 16) {
        float* srow = scores + rr * SC_PITCH;
        float vals[16];
        float mx = -1e30f;
        #pragma unroll
        for (int j = 0; j < 16; j++) {
            int k = lane + 32 * j;
            float v = srow[k] + mask_s[k];
            vals[j] = v;
            mx = fmaxf(mx, v);
        }
        #pragma unroll
        for (int o = 16; o > 0; o >>= 1) mx = fmaxf(mx, __shfl_xor_sync(0xffffffffu, mx, o));
        float sum = 0.f;
        #pragma unroll
        for (int j = 0; j < 16; j++) {
            float e = __expf(vals[j] - mx);
            srow[lane + 32 * j] = e;
            sum += e;
        }
        #pragma unroll
        for (int o = 16; o > 0; o >>= 1) sum += __shfl_xor_sync(0xffffffffu, sum, o);
        if (lane == 0) rinv_s[rr] = 1.0f / sum;
    }
    __syncthreads();

    // ---------------- Phase 3: PV (f32x2 over k-pairs, probs via LDS.128) ----
    float* outp = ks;   // reuse: [2][8][8][16]
    {
        const int h   = wid & 7;
        const int ks2 = wid >> 3;      // k-half
        const int e   = lane & 15;
        const int kk  = lane >> 4;     // 0/1
        const float* vbase = g_v + (size_t)(b * SS) * DD + h * 16 + e;
        const float* sbase = scores + h * SC_PITCH;

        unsigned long long acc2[8];
        #pragma unroll
        for (int q = 0; q < 8; q++) acc2[q] = 0ull;

        const int kstart = ks2 * 256 + kk * 4;
        #pragma unroll 4
        for (int i = 0; i < 32; i++) {
            const int k4 = kstart + i * 8;
            float v0 = vbase[(size_t)(k4 + 0) * DD];
            float v1 = vbase[(size_t)(k4 + 1) * DD];
            float v2 = vbase[(size_t)(k4 + 2) * DD];
            float v3 = vbase[(size_t)(k4 + 3) * DD];
            unsigned long long vp01 = pack2v(v0, v1);
            unsigned long long vp23 = pack2v(v2, v3);
            #pragma unroll
            for (int q = 0; q < 8; q++) {
                ulonglong2 p2 = *(const ulonglong2*)(sbase + q * 8 * SC_PITCH + k4);
                fma2(acc2[q], p2.x, vp01);
                fma2(acc2[q], p2.y, vp23);
            }
        }
        #pragma unroll
        for (int q = 0; q < 8; q++) {
            float lo, hi;
            unpack2(acc2[q], lo, hi);
            float s = lo + hi;
            s += __shfl_xor_sync(0xffffffffu, s, 16);
            if (lane < 16)
                outp[((ks2 * 8 + h) * 8 + q) * 16 + e] = s;
        }
    }
    __syncthreads();

    #pragma unroll
    for (int id = tid; id < 1024; id += 512) {
        int e = id & 15, q = (id >> 4) & 7, h = id >> 7;
        float val = (outp[((0 * 8 + h) * 8 + q) * 16 + e] +
                     outp[((1 * 8 + h) * 8 + q) * 16 + e]) * rinv_s[q * 8 + h];
        g_attn[(size_t)(b * SS + q0 + q) * DD + h * 16 + e] = val;
    }
}

// ---------------------------------------------------------------------------
// Kernel D: out = LN(residual + attn @ wo + bo). grid=128 (16 rows), block=256
// ---------------------------------------------------------------------------
__global__ __launch_bounds__(256) void out_ln_kernel(
    const float* __restrict__ x, const float* __restrict__ wo,
    const float* __restrict__ bo, const float* __restrict__ g,
    const float* __restrict__ bbeta, float* __restrict__ out)
{
    __shared__ float as_[16][128];
    __shared__ float ys[16][128];
    const int row0 = blockIdx.x * 16;
    const int t = threadIdx.x;

    #pragma unroll
    for (int i = t; i < 512; i += 256)
        ((float4*)as_)[i] = ((const float4*)(g_attn + (size_t)row0 * DD))[i];
    __syncthreads();

    const int c4 = t & 31;
    const int rg = t >> 5;   // rows rg*2, rg*2+1
    const ulonglong2* W2 = (const ulonglong2*)wo;

    unsigned long long acc[2][2];
    acc[0][0] = acc[0][1] = acc[1][0] = acc[1][1] = 0ull;

    #pragma unroll 8
    for (int d = 0; d < 128; d++) {
        ulonglong2 w = W2[d * 32 + c4];
        #pragma unroll
        for (int r = 0; r < 2; r++) {
            unsigned long long xr = pack2(as_[rg * 2 + r][d]);
            fma2(acc[r][0], xr, w.x);
            fma2(acc[r][1], xr, w.y);
        }
    }
    float4 bb = ((const float4*)bo)[c4];
    #pragma unroll
    for (int r = 0; r < 2; r++) {
        float4 o;
        unpack2(acc[r][0], o.x, o.y);
        unpack2(acc[r][1], o.z, o.w);
        float4 xr = ((const float4*)(x + (size_t)(row0 + rg * 2 + r) * DD))[c4];
        o.x += bb.x + xr.x; o.y += bb.y + xr.y;
        o.z += bb.z + xr.z; o.w += bb.w + xr.w;
        ((float4*)ys[rg * 2 + r])[c4] = o;
    }
    __syncthreads();

    // LayerNorm: 8 warps, 2 rows each
    const int wid = t >> 5, lane = t & 31;
    #pragma unroll
    for (int r = 0; r < 2; r++) {
        const int row = wid * 2 + r;
        float4 v = ((float4*)ys[row])[lane];
        float s = v.x + v.y + v.z + v.w;
        #pragma unroll
        for (int o = 16; o > 0; o >>= 1) s += __shfl_xor_sync(0xffffffffu, s, o);
        float mu = s * (1.f / 128.f);
        float dx = v.x - mu, dy = v.y - mu, dz = v.z - mu, dw = v.w - mu;
        float ss = dx * dx + dy * dy + dz * dz + dw * dw;
        #pragma unroll
        for (int o = 16; o > 0; o >>= 1) ss += __shfl_xor_sync(0xffffffffu, ss, o);
        float rstd = rsqrtf(ss * (1.f / 128.f) + 1e-5f);
        float4 gg = ((const float4*)g)[lane];
        float4 bb2 = ((const float4*)bbeta)[lane];
        float4 o4;
        o4.x = dx * rstd * gg.x + bb2.x;
        o4.y = dy * rstd * gg.y + bb2.y;
        o4.z = dz * rstd * gg.z + bb2.z;
        o4.w = dw * rstd * gg.w + bb2.w;
        ((float4*)(out + (size_t)(row0 + row) * DD))[lane] = o4;
    }
}

// ---------------------------------------------------------------------------
extern "C" void kernel_launch(void* const* d_in, const int* in_sizes, int n_in,
                              void* d_out, int out_size)
{
    const float* x    = (const float*)d_in[0];
    const float* st   = (const float*)d_in[1];
    const int*   mask = (const int*)  d_in[2];
    const float* wq   = (const float*)d_in[3];
    const float* bq   = (const float*)d_in[4];
    const float* wk   = (const float*)d_in[5];
    const float* bk   = (const float*)d_in[6];
    const float* wv   = (const float*)d_in[7];
    const float* bv   = (const float*)d_in[8];
    const float* wo   = (const float*)d_in[9];
    const float* bo   = (const float*)d_in[10];
    const float* wst  = (const float*)d_in[11];
    const float* lng  = (const float*)d_in[12];
    const float* lnb  = (const float*)d_in[13];
    float* out = (float*)d_out;

    const int SMEM_BIAS = (1024 + 8 * 2 * STG_F) * 4;                             // 139264 B
    const int SMEM_ATTN = (8 * 8 * SC_PITCH + 8 * 128 + 512 + 64 + 64 * 132) * 4; // 172288 B
    cudaFuncSetAttribute(bias_kernel, cudaFuncAttributeMaxDynamicSharedMemorySize, SMEM_BIAS);
    cudaFuncSetAttribute(attn_kernel, cudaFuncAttributeMaxDynamicSharedMemorySize, SMEM_ATTN);

    bias_kernel<<<BIAS_GRID, 256, SMEM_BIAS>>>(st, wst);
    qkv_kernel<<<128, 384>>>(x, wq, bq, wk, bk, wv, bv);
    attn_kernel<<<256, 512, SMEM_ATTN>>>(mask);
    out_ln_kernel<<<128, 256>>>(x, wo, bo, lng, lnb, out);
}